// round 1
// baseline (speedup 1.0000x reference)
#include <cuda_runtime.h>
#include <cstdint>
#include <cstddef>

// LSTM autoencoder, fully fused persistent kernel.
// B=256, T=1024, H=64, D_IN=D_OUT=128, gates G=4H=256.
// Grid: 128 CTAs x 256 threads; each CTA owns 2 batch elements end-to-end.
// Layer-0 weights in registers (f32x2 packed), layer-1 + FC weights in smem fp32.

#define Tn   1024
#define Hn   64
#define DINn 128
#define Gn   256

// shared memory layout (float offsets)
#define OFF_W1   0          // [256][132]  layer-1 cat(Wih1|Whh1), pitch 132
#define OFF_FC   33792      // [128][68]   fc_W, pitch 68
#define OFF_FCB  42496      // [128]       fc_b
#define OFF_X    42624      // enc: x stage [2][2][128]; dec: pred buf [2][128]
#define OFF_V    43136      // [2][128]    per-batch [h0(64) | h1(64)]
#define OFF_G    43392      // [2][256]    gate scratch
#define SMEM_FLOATS 43904   // 175616 bytes

__device__ __forceinline__ void fma2(unsigned long long& acc,
                                     unsigned long long a, unsigned long long b) {
    asm("fma.rn.f32x2 %0, %1, %2, %3;" : "=l"(acc) : "l"(a), "l"(b), "l"(acc));
}
__device__ __forceinline__ float psum(unsigned long long v) {
    float lo, hi;
    asm("mov.b64 {%0, %1}, %2;" : "=f"(lo), "=f"(hi) : "l"(v));
    return lo + hi;
}
__device__ __forceinline__ float sigm_f(float v) {
    return __fdividef(1.f, 1.f + __expf(-v));
}
__device__ __forceinline__ float tanh_f(float v) {
    float a = fabsf(v);
    float e = __expf(-2.f * a);
    float r = __fdividef(1.f - e, 1.f + e);
    return v < 0.f ? -r : r;
}
__device__ __forceinline__ float cellact(float gi, float gf, float gg, float go, float& c) {
    c = sigm_f(gf) * c + sigm_f(gi) * tanh_f(gg);
    return sigm_f(go) * tanh_f(c);
}

// gate preactivation: 128-elem x-part + 64-elem h-part, weights in registers
__device__ __forceinline__ float dot192(const unsigned long long (&w)[96],
                                        const float* xs, const float* hs, float bias) {
    unsigned long long a0 = 0ull, a1 = 0ull;
    const ulonglong2* xp = (const ulonglong2*)xs;
    #pragma unroll
    for (int i = 0; i < 32; i++) {
        ulonglong2 v = xp[i];
        fma2(a0, w[2 * i], v.x);
        fma2(a1, w[2 * i + 1], v.y);
    }
    const ulonglong2* hp = (const ulonglong2*)hs;
    #pragma unroll
    for (int i = 0; i < 16; i++) {
        ulonglong2 v = hp[i];
        fma2(a0, w[64 + 2 * i], v.x);
        fma2(a1, w[65 + 2 * i], v.y);
    }
    return psum(a0) + psum(a1) + bias;
}

__global__ void __launch_bounds__(256, 1)
lstm_ae_kernel(const float* __restrict__ x,
               const float* __restrict__ eW0i, const float* __restrict__ eW0h,
               const float* __restrict__ eb0i, const float* __restrict__ eb0h,
               const float* __restrict__ eW1i, const float* __restrict__ eW1h,
               const float* __restrict__ eb1i, const float* __restrict__ eb1h,
               const float* __restrict__ dW0i, const float* __restrict__ dW0h,
               const float* __restrict__ db0i, const float* __restrict__ db0h,
               const float* __restrict__ dW1i, const float* __restrict__ dW1h,
               const float* __restrict__ db1i, const float* __restrict__ db1h,
               const float* __restrict__ fcW,  const float* __restrict__ fcb,
               float* __restrict__ out)
{
    extern __shared__ float sm[];
    float* sW1  = sm + OFF_W1;
    float* sFC  = sm + OFF_FC;
    float* sFCb = sm + OFF_FCB;
    float* sX   = sm + OFF_X;
    float* sV   = sm + OFF_V;
    float* sG   = sm + OFF_G;

    const int t  = threadIdx.x;
    const int b0 = blockIdx.x * 2;
    const int aj = t & 63;
    const int ab = (t >> 6) & 1;

    unsigned long long w0[96];       // layer-0 weights for gate t (192 floats packed)
    float c0 = 0.f, c1 = 0.f;        // cell state for task (aj, ab), threads < 128

    // ================= encoder weight staging =================
    {
        const ulonglong2* p = (const ulonglong2*)(eW0i + t * 128);
        #pragma unroll
        for (int i = 0; i < 32; i++) { ulonglong2 v = p[i]; w0[2*i] = v.x; w0[2*i+1] = v.y; }
        const ulonglong2* q = (const ulonglong2*)(eW0h + t * 64);
        #pragma unroll
        for (int i = 0; i < 16; i++) { ulonglong2 v = q[i]; w0[64+2*i] = v.x; w0[65+2*i] = v.y; }
    }
    float bias0 = eb0i[t] + eb0h[t];
    float bias1 = eb1i[t] + eb1h[t];
    for (int idx = t; idx < 256 * 64; idx += 256) {
        int g = idx >> 6, k = idx & 63;
        sW1[g * 132 + k]      = eW1i[idx];
        sW1[g * 132 + 64 + k] = eW1h[idx];
    }
    sV[t] = 0.f;   // zero h0,h1 for both batch elems (256 floats)

    // prefetch x for steps 0 and 1
    #pragma unroll
    for (int s = 0; s < 2; s++) {
        if (t < 64) {
            int e = t >> 5, lane = t & 31;
            const float* src = x + ((size_t)(b0 + e) * Tn + s) * 128 + lane * 4;
            uint32_t dst = (uint32_t)__cvta_generic_to_shared(sX + (s * 2 + e) * 128 + lane * 4);
            asm volatile("cp.async.cg.shared.global [%0], [%1], 16;" :: "r"(dst), "l"(src) : "memory");
        }
        asm volatile("cp.async.commit_group;" ::: "memory");
    }
    __syncthreads();

    // ================= encoder loop =================
    for (int step = 0; step < Tn; step++) {
        asm volatile("cp.async.wait_group 1;" ::: "memory");
        __syncthreads();

        // layer 0 gates (both batch elems, weights in regs)
        {
            const float* xs0 = sX + ((step & 1) * 2 + 0) * 128;
            const float* xs1 = sX + ((step & 1) * 2 + 1) * 128;
            float ga = dot192(w0, xs0, sV, bias0);
            float gb = dot192(w0, xs1, sV + 128, bias0);
            sG[t] = ga; sG[256 + t] = gb;
        }
        __syncthreads();

        // prefetch step+2 into the buffer just freed
        if (t < 64 && step + 2 < Tn) {
            int e = t >> 5, lane = t & 31;
            const float* src = x + ((size_t)(b0 + e) * Tn + (step + 2)) * 128 + lane * 4;
            uint32_t dst = (uint32_t)__cvta_generic_to_shared(sX + ((step & 1) * 2 + e) * 128 + lane * 4);
            asm volatile("cp.async.cg.shared.global [%0], [%1], 16;" :: "r"(dst), "l"(src) : "memory");
        }
        asm volatile("cp.async.commit_group;" ::: "memory");

        // layer 0 activation -> h0 in sV[b][0:64]
        if (t < 128) {
            const float* g = sG + ab * 256;
            float h = cellact(g[aj], g[64 + aj], g[128 + aj], g[192 + aj], c0);
            sV[ab * 128 + aj] = h;
        }
        __syncthreads();

        // layer 1 gates (smem weights, amortized over both batch elems)
        {
            const ulonglong2* wp = (const ulonglong2*)(sW1 + t * 132);
            const ulonglong2* u0 = (const ulonglong2*)(sV);
            const ulonglong2* u1 = (const ulonglong2*)(sV + 128);
            unsigned long long a00 = 0, a01 = 0, a10 = 0, a11 = 0;
            #pragma unroll
            for (int i = 0; i < 32; i++) {
                ulonglong2 w = wp[i]; ulonglong2 p0 = u0[i]; ulonglong2 p1 = u1[i];
                fma2(a00, w.x, p0.x); fma2(a01, w.y, p0.y);
                fma2(a10, w.x, p1.x); fma2(a11, w.y, p1.y);
            }
            sG[t]       = psum(a00) + psum(a01) + bias1;
            sG[256 + t] = psum(a10) + psum(a11) + bias1;
        }
        __syncthreads();

        // layer 1 activation -> h1 in sV[b][64:128]
        if (t < 128) {
            const float* g = sG + ab * 256;
            float h = cellact(g[aj], g[64 + aj], g[128 + aj], g[192 + aj], c1);
            sV[ab * 128 + 64 + aj] = h;
        }
        __syncthreads();
    }

    // ================= transition: tanh states, load decoder weights =================
    asm volatile("cp.async.wait_group 0;" ::: "memory");
    if (t < 128) {
        c0 = tanh_f(c0);
        c1 = tanh_f(c1);
        sV[ab * 128 + aj]      = tanh_f(sV[ab * 128 + aj]);
        sV[ab * 128 + 64 + aj] = tanh_f(sV[ab * 128 + 64 + aj]);
    }
    sX[t] = 0.f;   // decoder x0 = zeros (pred buffer, 256 floats)
    {
        const ulonglong2* p = (const ulonglong2*)(dW0i + t * 128);
        #pragma unroll
        for (int i = 0; i < 32; i++) { ulonglong2 v = p[i]; w0[2*i] = v.x; w0[2*i+1] = v.y; }
        const ulonglong2* q = (const ulonglong2*)(dW0h + t * 64);
        #pragma unroll
        for (int i = 0; i < 16; i++) { ulonglong2 v = q[i]; w0[64+2*i] = v.x; w0[65+2*i] = v.y; }
    }
    bias0 = db0i[t] + db0h[t];
    bias1 = db1i[t] + db1h[t];
    for (int idx = t; idx < 256 * 64; idx += 256) {
        int g = idx >> 6, k = idx & 63;
        sW1[g * 132 + k]      = dW1i[idx];
        sW1[g * 132 + 64 + k] = dW1h[idx];
    }
    for (int idx = t; idx < 128 * 64; idx += 256) {
        int o = idx >> 6, k = idx & 63;
        sFC[o * 68 + k] = fcW[idx];
    }
    if (t < 128) sFCb[t] = fcb[t];
    __syncthreads();

    // ================= decoder loop (autoregressive) =================
    for (int step = 0; step < Tn; step++) {
        // layer 0 gates: input = prev pred (sX), hidden = sV[b][0:64]
        {
            float ga = dot192(w0, sX,       sV,       bias0);
            float gb = dot192(w0, sX + 128, sV + 128, bias0);
            sG[t] = ga; sG[256 + t] = gb;
        }
        __syncthreads();

        if (t < 128) {
            const float* g = sG + ab * 256;
            float h = cellact(g[aj], g[64 + aj], g[128 + aj], g[192 + aj], c0);
            sV[ab * 128 + aj] = h;
        }
        __syncthreads();

        // layer 1 gates
        {
            const ulonglong2* wp = (const ulonglong2*)(sW1 + t * 132);
            const ulonglong2* u0 = (const ulonglong2*)(sV);
            const ulonglong2* u1 = (const ulonglong2*)(sV + 128);
            unsigned long long a00 = 0, a01 = 0, a10 = 0, a11 = 0;
            #pragma unroll
            for (int i = 0; i < 32; i++) {
                ulonglong2 w = wp[i]; ulonglong2 p0 = u0[i]; ulonglong2 p1 = u1[i];
                fma2(a00, w.x, p0.x); fma2(a01, w.y, p0.y);
                fma2(a10, w.x, p1.x); fma2(a11, w.y, p1.y);
            }
            sG[t]       = psum(a00) + psum(a01) + bias1;
            sG[256 + t] = psum(a10) + psum(a11) + bias1;
        }
        __syncthreads();

        if (t < 128) {
            const float* g = sG + ab * 256;
            float h = cellact(g[aj], g[64 + aj], g[128 + aj], g[192 + aj], c1);
            sV[ab * 128 + 64 + aj] = h;
        }
        __syncthreads();

        // fc: pred = h1 @ fc_W.T + fc_b ; write out + feed back
        {
            int o = t & 127, bb = t >> 7;
            const ulonglong2* wp = (const ulonglong2*)(sFC + o * 68);
            const ulonglong2* hp = (const ulonglong2*)(sV + bb * 128 + 64);
            unsigned long long a0 = 0, a1 = 0;
            #pragma unroll
            for (int i = 0; i < 16; i++) {
                ulonglong2 w = wp[i]; ulonglong2 h = hp[i];
                fma2(a0, w.x, h.x);
                fma2(a1, w.y, h.y);
            }
            float p = psum(a0) + psum(a1) + sFCb[o];
            out[((size_t)(b0 + bb) * Tn + step) * 128 + o] = p;
            sX[bb * 128 + o] = p;
        }
        __syncthreads();
    }
}

extern "C" void kernel_launch(void* const* d_in, const int* in_sizes, int n_in,
                              void* d_out, int out_size) {
    (void)in_sizes; (void)n_in; (void)out_size;
    const float* x    = (const float*)d_in[0];
    const float* eW0i = (const float*)d_in[1];
    const float* eW0h = (const float*)d_in[2];
    const float* eb0i = (const float*)d_in[3];
    const float* eb0h = (const float*)d_in[4];
    const float* eW1i = (const float*)d_in[5];
    const float* eW1h = (const float*)d_in[6];
    const float* eb1i = (const float*)d_in[7];
    const float* eb1h = (const float*)d_in[8];
    const float* dW0i = (const float*)d_in[9];
    const float* dW0h = (const float*)d_in[10];
    const float* db0i = (const float*)d_in[11];
    const float* db0h = (const float*)d_in[12];
    const float* dW1i = (const float*)d_in[13];
    const float* dW1h = (const float*)d_in[14];
    const float* db1i = (const float*)d_in[15];
    const float* db1h = (const float*)d_in[16];
    const float* fcW  = (const float*)d_in[17];
    const float* fcb  = (const float*)d_in[18];

    cudaFuncSetAttribute(lstm_ae_kernel, cudaFuncAttributeMaxDynamicSharedMemorySize,
                         SMEM_FLOATS * (int)sizeof(float));
    lstm_ae_kernel<<<128, 256, SMEM_FLOATS * sizeof(float)>>>(
        x, eW0i, eW0h, eb0i, eb0h, eW1i, eW1h, eb1i, eb1h,
        dW0i, dW0h, db0i, db0h, dW1i, dW1h, db1i, db1h,
        fcW, fcb, (float*)d_out);
}

// round 2
// speedup vs baseline: 1.0579x; 1.0579x over previous
#include <cuda_runtime.h>
#include <cstdint>
#include <cstddef>

// LSTM autoencoder, fused persistent kernel, round 2.
// B=256, T=1024, H=64, D_IN=D_OUT=128, G=4H=256.
// 128 CTAs x 256 threads; each CTA owns 2 batch elements end-to-end.
//
// R2 changes vs R1:
//  - decoder FC folded into L0 input transform via precomputed M = dec_Wih0 @ fcW
//    (removes pred->L0 dependency; decoder L0 k=128 all-register; FC off critical path)
//  - h1_prev @ Whh1 computed in parallel with L0 gates (both phases)
//  - decoder Wih1 (k=64) register-resident; only Whh1 + FC remain in smem
//  - 4 barriers/step

#define Tn   1024

// shared memory layout (float offsets)
#define OFF_W1   0          // enc: [256][132] cat(Wih1|Whh1); dec: Whh1 [256][68]
#define OFF_FC   33792      // [128][68] fc_W
#define OFF_FCB  42496      // [128] fc_b
#define OFF_X    42624      // enc x stage [2][2][128]
#define OFF_V    43136      // [2][128] per-batch [h0(64)|h1(64)]
#define OFF_G    43392      // [2][256] gate scratch
#define SMEM_FLOATS 43904   // 175616 bytes

__device__ __align__(16) float g_M[256 * 64];   // dec_Wih0 @ fcW  [gate][j]

__device__ __forceinline__ void fma2(unsigned long long& acc,
                                     unsigned long long a, unsigned long long b) {
    asm("fma.rn.f32x2 %0, %1, %2, %3;" : "=l"(acc) : "l"(a), "l"(b), "l"(acc));
}
__device__ __forceinline__ float psum(unsigned long long v) {
    float lo, hi;
    asm("mov.b64 {%0, %1}, %2;" : "=f"(lo), "=f"(hi) : "l"(v));
    return lo + hi;
}
__device__ __forceinline__ float sigm_f(float v) {
    return __fdividef(1.f, 1.f + __expf(-v));
}
__device__ __forceinline__ float tanh_f(float v) {
    float a = fabsf(v);
    float e = __expf(-2.f * a);
    float r = __fdividef(1.f - e, 1.f + e);
    return v < 0.f ? -r : r;
}
__device__ __forceinline__ float cellact(float gi, float gf, float gg, float go, float& c) {
    c = sigm_f(gf) * c + sigm_f(gi) * tanh_f(gg);
    return sigm_f(go) * tanh_f(c);
}

// encoder L0 preactivation: 128-elem x-part + 64-elem h-part, weights in regs
__device__ __forceinline__ float dot192(const unsigned long long (&w)[96],
                                        const float* xs, const float* hs, float bias) {
    unsigned long long a0 = 0ull, a1 = 0ull;
    const ulonglong2* xp = (const ulonglong2*)xs;
    #pragma unroll
    for (int i = 0; i < 32; i++) {
        ulonglong2 v = xp[i];
        fma2(a0, w[2 * i], v.x);
        fma2(a1, w[2 * i + 1], v.y);
    }
    const ulonglong2* hp = (const ulonglong2*)hs;
    #pragma unroll
    for (int i = 0; i < 16; i++) {
        ulonglong2 v = hp[i];
        fma2(a0, w[64 + 2 * i], v.x);
        fma2(a1, w[65 + 2 * i], v.y);
    }
    return psum(a0) + psum(a1) + bias;
}

__global__ void prep_kernel(const float* __restrict__ dW0i, const float* __restrict__ fcW) {
    int id = blockIdx.x * blockDim.x + threadIdx.x;  // 0..16383
    int g = id >> 6, j = id & 63;
    float acc = 0.f;
    #pragma unroll 4
    for (int d = 0; d < 128; d++)
        acc = fmaf(dW0i[g * 128 + d], fcW[d * 64 + j], acc);
    g_M[id] = acc;
}

__global__ void __launch_bounds__(256, 1)
lstm_ae_kernel(const float* __restrict__ x,
               const float* __restrict__ eW0i, const float* __restrict__ eW0h,
               const float* __restrict__ eb0i, const float* __restrict__ eb0h,
               const float* __restrict__ eW1i, const float* __restrict__ eW1h,
               const float* __restrict__ eb1i, const float* __restrict__ eb1h,
               const float* __restrict__ dW0i, const float* __restrict__ dW0h,
               const float* __restrict__ db0i, const float* __restrict__ db0h,
               const float* __restrict__ dW1i, const float* __restrict__ dW1h,
               const float* __restrict__ db1i, const float* __restrict__ db1h,
               const float* __restrict__ fcW,  const float* __restrict__ fcb,
               float* __restrict__ out)
{
    extern __shared__ float sm[];
    float* sW1  = sm + OFF_W1;
    float* sFC  = sm + OFF_FC;
    float* sFCb = sm + OFF_FCB;
    float* sX   = sm + OFF_X;
    float* sV   = sm + OFF_V;
    float* sG   = sm + OFF_G;

    const int t  = threadIdx.x;
    const int b0 = blockIdx.x * 2;
    const int aj = t & 63;
    const int ab = (t >> 6) & 1;

    float c0 = 0.f, c1 = 0.f;

    // ================= ENCODER =================
    {
        unsigned long long w0[96];   // enc L0: Wih0 row (128 fl) | Whh0 row (64 fl)
        {
            const ulonglong2* p = (const ulonglong2*)(eW0i + t * 128);
            #pragma unroll
            for (int i = 0; i < 32; i++) { ulonglong2 v = p[i]; w0[2*i] = v.x; w0[2*i+1] = v.y; }
            const ulonglong2* q = (const ulonglong2*)(eW0h + t * 64);
            #pragma unroll
            for (int i = 0; i < 16; i++) { ulonglong2 v = q[i]; w0[64+2*i] = v.x; w0[65+2*i] = v.y; }
        }
        float bias0 = eb0i[t] + eb0h[t];
        float bias1 = eb1i[t] + eb1h[t];
        for (int idx = t; idx < 256 * 64; idx += 256) {
            int g = idx >> 6, k = idx & 63;
            sW1[g * 132 + k]      = eW1i[idx];
            sW1[g * 132 + 64 + k] = eW1h[idx];
        }
        sV[t] = 0.f;

        // prefetch x steps 0,1
        #pragma unroll
        for (int s = 0; s < 2; s++) {
            if (t < 64) {
                int e = t >> 5, lane = t & 31;
                const float* src = x + ((size_t)(b0 + e) * Tn + s) * 128 + lane * 4;
                uint32_t dst = (uint32_t)__cvta_generic_to_shared(sX + (s * 2 + e) * 128 + lane * 4);
                asm volatile("cp.async.cg.shared.global [%0], [%1], 16;" :: "r"(dst), "l"(src) : "memory");
            }
            asm volatile("cp.async.commit_group;" ::: "memory");
        }
        asm volatile("cp.async.wait_group 1;" ::: "memory");
        __syncthreads();

        for (int step = 0; step < Tn; step++) {
            // P1: L0 gates + h1part (h1_prev @ Whh1)
            float p0, p1;
            {
                const float* xs0 = sX + ((step & 1) * 2) * 128;
                float ga = dot192(w0, xs0,       sV,       bias0);
                float gb = dot192(w0, xs0 + 128, sV + 128, bias0);
                const ulonglong2* wp  = (const ulonglong2*)(sW1 + t * 132 + 64);
                const ulonglong2* h1a = (const ulonglong2*)(sV + 64);
                const ulonglong2* h1b = (const ulonglong2*)(sV + 192);
                unsigned long long q00 = 0, q01 = 0, q10 = 0, q11 = 0;
                #pragma unroll
                for (int i = 0; i < 16; i++) {
                    ulonglong2 w = wp[i]; ulonglong2 va = h1a[i]; ulonglong2 vb = h1b[i];
                    fma2(q00, w.x, va.x); fma2(q01, w.y, va.y);
                    fma2(q10, w.x, vb.x); fma2(q11, w.y, vb.y);
                }
                p0 = psum(q00) + psum(q01);
                p1 = psum(q10) + psum(q11);
                sG[t] = ga; sG[256 + t] = gb;
            }
            __syncthreads();

            // P2: act0 + prefetch step+2
            if (t < 128) {
                const float* g = sG + ab * 256;
                sV[ab * 128 + aj] = cellact(g[aj], g[64 + aj], g[128 + aj], g[192 + aj], c0);
            }
            if (t < 64 && step + 2 < Tn) {
                int e = t >> 5, lane = t & 31;
                const float* src = x + ((size_t)(b0 + e) * Tn + (step + 2)) * 128 + lane * 4;
                uint32_t dst = (uint32_t)__cvta_generic_to_shared(sX + ((step & 1) * 2 + e) * 128 + lane * 4);
                asm volatile("cp.async.cg.shared.global [%0], [%1], 16;" :: "r"(dst), "l"(src) : "memory");
            }
            asm volatile("cp.async.commit_group;" ::: "memory");
            __syncthreads();

            // P3: L1 gates = h0 @ Wih1 + h1part
            {
                const ulonglong2* wp  = (const ulonglong2*)(sW1 + t * 132);
                const ulonglong2* h0a = (const ulonglong2*)(sV);
                const ulonglong2* h0b = (const ulonglong2*)(sV + 128);
                unsigned long long q00 = 0, q01 = 0, q10 = 0, q11 = 0;
                #pragma unroll
                for (int i = 0; i < 16; i++) {
                    ulonglong2 w = wp[i]; ulonglong2 va = h0a[i]; ulonglong2 vb = h0b[i];
                    fma2(q00, w.x, va.x); fma2(q01, w.y, va.y);
                    fma2(q10, w.x, vb.x); fma2(q11, w.y, vb.y);
                }
                sG[t]       = psum(q00) + psum(q01) + p0 + bias1;
                sG[256 + t] = psum(q10) + psum(q11) + p1 + bias1;
            }
            __syncthreads();

            // P4: act1
            if (t < 128) {
                const float* g = sG + ab * 256;
                sV[ab * 128 + 64 + aj] = cellact(g[aj], g[64 + aj], g[128 + aj], g[192 + aj], c1);
            }
            asm volatile("cp.async.wait_group 1;" ::: "memory");
            __syncthreads();
        }
        asm volatile("cp.async.wait_group 0;" ::: "memory");
    }

    // ================= TRANSITION =================
    if (t < 128) {
        c0 = tanh_f(c0);
        c1 = tanh_f(c1);
        sV[ab * 128 + aj]      = tanh_f(sV[ab * 128 + aj]);
        sV[ab * 128 + 64 + aj] = tanh_f(sV[ab * 128 + 64 + aj]);
    }
    unsigned long long wA[64];  // [0..31] M row (64 fl over h1), [32..63] Whh0 row (64 fl over h0)
    unsigned long long wC[32];  // Wih1 row (64 fl over h0)
    {
        const ulonglong2* p = (const ulonglong2*)(g_M + t * 64);
        #pragma unroll
        for (int i = 0; i < 16; i++) { ulonglong2 v = p[i]; wA[2*i] = v.x; wA[2*i+1] = v.y; }
        const ulonglong2* q = (const ulonglong2*)(dW0h + t * 64);
        #pragma unroll
        for (int i = 0; i < 16; i++) { ulonglong2 v = q[i]; wA[32+2*i] = v.x; wA[33+2*i] = v.y; }
        const ulonglong2* r = (const ulonglong2*)(dW1i + t * 64);
        #pragma unroll
        for (int i = 0; i < 16; i++) { ulonglong2 v = r[i]; wC[2*i] = v.x; wC[2*i+1] = v.y; }
    }
    float bias0 = db0i[t] + db0h[t];
    float b0fold;
    {
        float a = 0.f;
        #pragma unroll 4
        for (int d = 0; d < 128; d++) a = fmaf(dW0i[t * 128 + d], fcb[d], a);
        b0fold = bias0 + a;   // bias0 + Wih0 @ fcb
    }
    float bias1 = db1i[t] + db1h[t];
    for (int idx = t; idx < 256 * 64; idx += 256) {
        int g = idx >> 6, k = idx & 63;
        sW1[g * 68 + k] = dW1h[idx];       // Whh1, pitch 68
    }
    for (int idx = t; idx < 128 * 64; idx += 256) {
        int o = idx >> 6, k = idx & 63;
        sFC[o * 68 + k] = fcW[idx];
    }
    if (t < 128) sFCb[t] = fcb[t];
    __syncthreads();

    // ================= DECODER =================
    for (int step = 0; step < Tn; step++) {
        // P1: L0 gates = h1_prev@M + h0_prev@Whh0 + b0fold (step 0: no M term, plain bias)
        //     + deferred FC(h1_prev) -> out[step-1]
        {
            const ulonglong2* h0a = (const ulonglong2*)(sV);
            const ulonglong2* h0b = (const ulonglong2*)(sV + 128);
            const ulonglong2* h1a = (const ulonglong2*)(sV + 64);
            const ulonglong2* h1b = (const ulonglong2*)(sV + 192);
            unsigned long long qa0 = 0, qa1 = 0, qb0 = 0, qb1 = 0;
            #pragma unroll
            for (int i = 0; i < 16; i++) {
                ulonglong2 va = h0a[i]; ulonglong2 vb = h0b[i];
                fma2(qa0, wA[32 + 2*i], va.x); fma2(qa1, wA[33 + 2*i], va.y);
                fma2(qb0, wA[32 + 2*i], vb.x); fma2(qb1, wA[33 + 2*i], vb.y);
            }
            float ga, gb;
            if (step > 0) {
                #pragma unroll
                for (int i = 0; i < 16; i++) {
                    ulonglong2 va = h1a[i]; ulonglong2 vb = h1b[i];
                    fma2(qa0, wA[2*i], va.x); fma2(qa1, wA[2*i+1], va.y);
                    fma2(qb0, wA[2*i], vb.x); fma2(qb1, wA[2*i+1], vb.y);
                }
                ga = psum(qa0) + psum(qa1) + b0fold;
                gb = psum(qb0) + psum(qb1) + b0fold;
                // deferred FC of previous h1
                int o = t & 127, bb = t >> 7;
                const ulonglong2* wp = (const ulonglong2*)(sFC + o * 68);
                const ulonglong2* hp = bb ? h1b : h1a;
                unsigned long long f0 = 0, f1 = 0;
                #pragma unroll
                for (int i = 0; i < 16; i++) {
                    ulonglong2 w = wp[i]; ulonglong2 h = hp[i];
                    fma2(f0, w.x, h.x); fma2(f1, w.y, h.y);
                }
                float pr = psum(f0) + psum(f1) + sFCb[o];
                out[((size_t)(b0 + bb) * Tn + (step - 1)) * 128 + o] = pr;
            } else {
                ga = psum(qa0) + psum(qa1) + bias0;
                gb = psum(qb0) + psum(qb1) + bias0;
            }
            sG[t] = ga; sG[256 + t] = gb;
        }
        __syncthreads();

        // P2: act0 + h1part (h1_prev @ Whh1 from smem)
        float p0, p1;
        {
            const ulonglong2* wp  = (const ulonglong2*)(sW1 + t * 68);
            const ulonglong2* h1a = (const ulonglong2*)(sV + 64);
            const ulonglong2* h1b = (const ulonglong2*)(sV + 192);
            unsigned long long q00 = 0, q01 = 0, q10 = 0, q11 = 0;
            #pragma unroll
            for (int i = 0; i < 16; i++) {
                ulonglong2 w = wp[i]; ulonglong2 va = h1a[i]; ulonglong2 vb = h1b[i];
                fma2(q00, w.x, va.x); fma2(q01, w.y, va.y);
                fma2(q10, w.x, vb.x); fma2(q11, w.y, vb.y);
            }
            p0 = psum(q00) + psum(q01);
            p1 = psum(q10) + psum(q11);
        }
        if (t < 128) {
            const float* g = sG + ab * 256;
            sV[ab * 128 + aj] = cellact(g[aj], g[64 + aj], g[128 + aj], g[192 + aj], c0);
        }
        __syncthreads();

        // P3: L1 gates = h0 @ Wih1 (regs) + h1part
        {
            const ulonglong2* h0a = (const ulonglong2*)(sV);
            const ulonglong2* h0b = (const ulonglong2*)(sV + 128);
            unsigned long long q00 = 0, q01 = 0, q10 = 0, q11 = 0;
            #pragma unroll
            for (int i = 0; i < 16; i++) {
                ulonglong2 va = h0a[i]; ulonglong2 vb = h0b[i];
                fma2(q00, wC[2*i], va.x); fma2(q01, wC[2*i+1], va.y);
                fma2(q10, wC[2*i], vb.x); fma2(q11, wC[2*i+1], vb.y);
            }
            sG[t]       = psum(q00) + psum(q01) + p0 + bias1;
            sG[256 + t] = psum(q10) + psum(q11) + p1 + bias1;
        }
        __syncthreads();

        // P4: act1
        if (t < 128) {
            const float* g = sG + ab * 256;
            sV[ab * 128 + 64 + aj] = cellact(g[aj], g[64 + aj], g[128 + aj], g[192 + aj], c1);
        }
        __syncthreads();
    }

    // final FC for last step's h1
    {
        int o = t & 127, bb = t >> 7;
        const ulonglong2* wp = (const ulonglong2*)(sFC + o * 68);
        const ulonglong2* hp = (const ulonglong2*)(sV + bb * 128 + 64);
        unsigned long long f0 = 0, f1 = 0;
        #pragma unroll
        for (int i = 0; i < 16; i++) {
            ulonglong2 w = wp[i]; ulonglong2 h = hp[i];
            fma2(f0, w.x, h.x); fma2(f1, w.y, h.y);
        }
        float pr = psum(f0) + psum(f1) + sFCb[o];
        out[((size_t)(b0 + bb) * Tn + (Tn - 1)) * 128 + o] = pr;
    }
}

extern "C" void kernel_launch(void* const* d_in, const int* in_sizes, int n_in,
                              void* d_out, int out_size) {
    (void)in_sizes; (void)n_in; (void)out_size;
    const float* x    = (const float*)d_in[0];
    const float* eW0i = (const float*)d_in[1];
    const float* eW0h = (const float*)d_in[2];
    const float* eb0i = (const float*)d_in[3];
    const float* eb0h = (const float*)d_in[4];
    const float* eW1i = (const float*)d_in[5];
    const float* eW1h = (const float*)d_in[6];
    const float* eb1i = (const float*)d_in[7];
    const float* eb1h = (const float*)d_in[8];
    const float* dW0i = (const float*)d_in[9];
    const float* dW0h = (const float*)d_in[10];
    const float* db0i = (const float*)d_in[11];
    const float* db0h = (const float*)d_in[12];
    const float* dW1i = (const float*)d_in[13];
    const float* dW1h = (const float*)d_in[14];
    const float* db1i = (const float*)d_in[15];
    const float* db1h = (const float*)d_in[16];
    const float* fcW  = (const float*)d_in[17];
    const float* fcb  = (const float*)d_in[18];

    prep_kernel<<<64, 256>>>(dW0i, fcW);

    cudaFuncSetAttribute(lstm_ae_kernel, cudaFuncAttributeMaxDynamicSharedMemorySize,
                         SMEM_FLOATS * (int)sizeof(float));
    lstm_ae_kernel<<<128, 256, SMEM_FLOATS * sizeof(float)>>>(
        x, eW0i, eW0h, eb0i, eb0h, eW1i, eW1h, eb1i, eb1h,
        dW0i, dW0h, db0i, db0h, dW1i, dW1h, db1i, db1h,
        fcW, fcb, (float*)d_out);
}